// round 4
// baseline (speedup 1.0000x reference)
#include <cuda_runtime.h>

#define T_STEPS 730
#define N_GRID  10000
#define LENF    15
#define NEARZERO 1e-5f
#define BLK   64            // threads per block; one thread per grid cell
#define GPB   64            // grid cells per block
#define CHUNK 7             // timesteps per cp.async stage (2 buffers -> 14/superstep)
#define NSUPER 53           // 53 * 14 = 742 >= 730
#define NCHUNKS 106

// Shared staging: [buf][step][data]
struct __align__(16) Smem {
    float sx[2][CHUNK][GPB * 3];   // P, Ta, PET per cell
    float sd[2][CHUNK][GPB * 4];   // parBETA(m0,m1), parBETAET(m0,m1) per cell
};

__device__ __forceinline__ void cp16(void* dst_smem, const void* src) {
    unsigned d = (unsigned)__cvta_generic_to_shared(dst_smem);
    asm volatile("cp.async.ca.shared.global [%0], [%1], 16;\n" :: "r"(d), "l"(src));
}

// Stage CHUNK timesteps (starting at t0) into buffer `buf`.
// Addresses clamped to tensor end; clamped data never used for output.
__device__ __forceinline__ void stage(
    Smem& s, int buf, int t0, int gb,
    const float* __restrict__ x_phy, const float* __restrict__ pdy, int c)
{
    const long limx = (long)T_STEPS * N_GRID * 3 - 4;
    #pragma unroll
    for (int v = 0; v < 6; ++v) {                 // CHUNK*48 = 336 vecs / 64 thr
        const int i = c + v * BLK;
        if (i < CHUNK * 48) {
            const int st = i / 48, o = i % 48;
            long idx = (long)(t0 + st) * (N_GRID * 3) + (long)gb * 3 + o * 4;
            if (idx > limx) idx = limx;
            cp16(&s.sx[buf][st][o * 4], x_phy + idx);
        }
    }
    const long limd = (long)T_STEPS * N_GRID * 4 - 4;
    #pragma unroll
    for (int v = 0; v < 7; ++v) {                 // CHUNK*64 = 448 vecs / 64 thr
        const int i = c + v * BLK;
        if (i < CHUNK * 64) {
            const int st = i >> 6, o = i & 63;
            long idx = (long)(t0 + st) * (N_GRID * 4) + (long)gb * 4 + o * 4;
            if (idx > limd) idx = limd;
            cp16(&s.sd[buf][st][o * 4], pdy + idx);
        }
    }
}

// Per-component HBV parameters + state (two of these per thread/cell)
struct Chain {
    float parFC, parK0, parK1, parK2, parPERC, parUZL, parTT,
          parCFMAX, parCWH, parC;
    float invFC, invLPFC, crf, gwcap;
    float snowpack, meltwater, sm, suz, slz;
};

// One HBV step for BOTH nmul components (explicitly interleaved for ILP)
// + inline 15-tap gamma-UH routing on the component mean.
// RP = t mod 14 (compile time) -> static routing-ring indexing.
template<int RP>
__device__ __forceinline__ void step_body(
    Chain (&C)[2], float (&w)[LENF], float (&qh)[LENF - 1],
    const Smem& sm_, int buf, int slot, int t,
    int lg, int g, bool active, float* __restrict__ out)
{
    const float P  = sm_.sx[buf][slot][lg * 3 + 0];
    const float Ta = sm_.sx[buf][slot][lg * 3 + 1];
    const float PE = sm_.sx[buf][slot][lg * 3 + 2];
    const float4 dp = *reinterpret_cast<const float4*>(&sm_.sd[buf][slot][lg * 4]);
    const float beta[2]   = { dp.x * 5.0f + 1.0f, dp.y * 5.0f + 1.0f };
    const float betaet[2] = { dp.z * 4.7f + 0.3f, dp.w * 4.7f + 0.3f };

    float qt[2];
    #pragma unroll
    for (int m = 0; m < 2; ++m) {
        Chain& S = C[m];
        // --- snow bucket ---
        const float rain = (Ta >= S.parTT) ? P : 0.0f;
        const float snow = P - rain;
        S.snowpack += snow;
        const float melt = fminf(fmaxf(S.parCFMAX * (Ta - S.parTT), 0.0f), S.snowpack);
        S.meltwater += melt;
        S.snowpack  -= melt;
        const float refr = fminf(fmaxf(S.crf * (S.parTT - Ta), 0.0f), S.meltwater);
        S.snowpack  += refr;
        S.meltwater -= refr;
        const float tosoil = fmaxf(S.meltwater - S.parCWH * S.snowpack, 0.0f);
        S.meltwater -= tosoil;

        // --- soil bucket ---
        const float swet = fminf(__powf(S.sm * S.invFC, beta[m]), 1.0f);
        const float rpt  = rain + tosoil;
        const float recharge = rpt * swet;
        S.sm += rpt - recharge;
        const float excess = fmaxf(S.sm - S.parFC, 0.0f);
        S.sm -= excess;
        const float efb = fminf(S.sm * S.invLPFC, 1.0f);
        const float ef  = __powf(efb, betaet[m]);
        const float et  = fminf(S.sm, PE * ef);
        S.sm = fmaxf(S.sm - et, NEARZERO);
        const float cap = fminf(S.slz, S.parC * S.slz * (1.0f - fminf(S.sm * S.invFC, 1.0f)));
        S.sm  = fmaxf(S.sm + cap, NEARZERO);
        S.slz = fmaxf(S.slz - cap, NEARZERO);

        // --- groundwater buckets ---
        S.suz += recharge + excess;
        const float perc = fminf(S.suz, S.parPERC);
        S.suz -= perc;
        const float q0 = S.parK0 * fmaxf(S.suz - S.parUZL, 0.0f);
        S.suz -= q0;
        const float q1 = S.parK1 * S.suz;
        S.suz -= q1;
        S.slz += perc;
        const float gwl = fminf(S.slz, S.gwcap);
        S.slz -= gwl;
        const float q2 = S.parK2 * S.slz;
        S.slz -= q2;
        qt[m] = q0 + q1 + q2;
    }

    const float qs = 0.5f * (qt[0] + qt[1]);   // mean over nmul (local, no shfl)

    // --- routing: flow[t] = w0*q[t] + sum_{k=1..14} w[k]*q[t-k] ---
    float flow = w[0] * qs;
    #pragma unroll
    for (int k = 1; k < LENF; ++k)
        flow += w[k] * qh[(RP + 14 - k) % 14];
    qh[RP] = qs;

    if (active && t < T_STEPS) out[t * N_GRID + g] = flow;
}

__global__ void __launch_bounds__(BLK) hbv_fused(
    const float* __restrict__ x_phy,   // [T, G, 3]
    const float* __restrict__ ac_all,  // [G]
    const float* __restrict__ pdy,     // [T, G, 2, 2]
    const float* __restrict__ pstat,   // [G, 30]
    float* __restrict__ out)           // [T, G]
{
    __shared__ Smem smem;

    const int gb  = blockIdx.x * GPB;
    const int lg  = threadIdx.x;            // cell index within block
    const int g   = gb + lg;
    const bool active = (g < N_GRID);
    const int gc  = active ? g : (N_GRID - 1);
    const int c   = threadIdx.x;

    // ---- static params for both components ----
    const float* ps = pstat + gc * 30;
    const float Ac = ac_all[gc];
    Chain C[2];
    #pragma unroll
    for (int m = 0; m < 2; ++m) {
        Chain& S = C[m];
        S.parFC    = ps[0*2+m]  * 950.0f  + 50.0f;
        S.parK0    = ps[1*2+m]  * 0.85f   + 0.05f;
        S.parK1    = ps[2*2+m]  * 0.49f   + 0.01f;
        S.parK2    = ps[3*2+m]  * 0.199f  + 0.001f;
        const float parLP = ps[4*2+m] * 0.8f + 0.2f;
        S.parPERC  = ps[5*2+m]  * 10.0f;
        S.parUZL   = ps[6*2+m]  * 100.0f;
        S.parTT    = ps[7*2+m]  * 5.0f    - 2.5f;
        S.parCFMAX = ps[8*2+m]  * 9.5f    + 0.5f;
        const float parCFR = ps[9*2+m] * 0.1f;
        S.parCWH   = ps[10*2+m] * 0.2f;
        S.parC     = ps[11*2+m];
        const float parRT = ps[12*2+m] * 20.0f;
        const float parAC = ps[13*2+m] * 2500.0f;
        S.invFC   = 1.0f / S.parFC;
        S.invLPFC = 1.0f / (parLP * S.parFC);
        S.crf     = parCFR * S.parCFMAX;
        S.gwcap   = parRT * fminf(fmaxf(1.0f - Ac / (parAC + NEARZERO), 0.0f), 1.0f);
        S.snowpack = S.meltwater = S.sm = S.suz = S.slz = 1e-3f;
    }

    // ---- normalized gamma-UH weights (lgamma & theta^-a cancel) ----
    const float a_r  = fmaxf(ps[28] * 2.9f, 0.0f) + 0.1f;
    const float th_r = fmaxf(ps[29] * 6.5f, 0.0f) + 0.5f;
    const float am1  = a_r - 1.0f;
    const float ivt  = 1.0f / th_r;
    const float LOGTK[LENF] = {
        -0.69314718f, 0.40546511f, 0.91629073f, 1.25276297f, 1.50407740f,
         1.70474809f, 1.87180218f, 2.01490302f, 2.14006616f, 2.25129180f,
         2.35137526f, 2.44234704f, 2.52572864f, 2.60268969f, 2.67414865f };
    float w[LENF];
    float wsum = 0.0f;
    #pragma unroll
    for (int k = 0; k < LENF; ++k) {
        const float tk = (float)k + 0.5f;
        w[k] = __expf(am1 * LOGTK[k] - tk * ivt);
        wsum += w[k];
    }
    const float ivw = 1.0f / wsum;
    #pragma unroll
    for (int k = 0; k < LENF; ++k) w[k] *= ivw;

    float qh[LENF - 1];
    #pragma unroll
    for (int k = 0; k < LENF - 1; ++k) qh[k] = 0.0f;

    // ---- pipeline prologue ----
    stage(smem, 0, 0,     gb, x_phy, pdy, c);
    asm volatile("cp.async.commit_group;\n");
    stage(smem, 1, CHUNK, gb, x_phy, pdy, c);
    asm volatile("cp.async.commit_group;\n");

    // ---- 53 super-iterations x 14 steps ----
    for (int it = 0; it < NSUPER; ++it) {
        const int t0 = it * 14;

        asm volatile("cp.async.wait_group 1;\n");
        __syncthreads();
        step_body< 0>(C, w, qh, smem, 0, 0, t0 + 0, lg, g, active, out);
        step_body< 1>(C, w, qh, smem, 0, 1, t0 + 1, lg, g, active, out);
        step_body< 2>(C, w, qh, smem, 0, 2, t0 + 2, lg, g, active, out);
        step_body< 3>(C, w, qh, smem, 0, 3, t0 + 3, lg, g, active, out);
        step_body< 4>(C, w, qh, smem, 0, 4, t0 + 4, lg, g, active, out);
        step_body< 5>(C, w, qh, smem, 0, 5, t0 + 5, lg, g, active, out);
        step_body< 6>(C, w, qh, smem, 0, 6, t0 + 6, lg, g, active, out);
        __syncthreads();
        {
            const int nch = it * 2 + 2;
            if (nch < NCHUNKS) stage(smem, 0, nch * CHUNK, gb, x_phy, pdy, c);
            asm volatile("cp.async.commit_group;\n");
        }

        asm volatile("cp.async.wait_group 1;\n");
        __syncthreads();
        step_body< 7>(C, w, qh, smem, 1, 0, t0 +  7, lg, g, active, out);
        step_body< 8>(C, w, qh, smem, 1, 1, t0 +  8, lg, g, active, out);
        step_body< 9>(C, w, qh, smem, 1, 2, t0 +  9, lg, g, active, out);
        step_body<10>(C, w, qh, smem, 1, 3, t0 + 10, lg, g, active, out);
        step_body<11>(C, w, qh, smem, 1, 4, t0 + 11, lg, g, active, out);
        step_body<12>(C, w, qh, smem, 1, 5, t0 + 12, lg, g, active, out);
        step_body<13>(C, w, qh, smem, 1, 6, t0 + 13, lg, g, active, out);
        __syncthreads();
        {
            const int nch = it * 2 + 3;
            if (nch < NCHUNKS) stage(smem, 1, nch * CHUNK, gb, x_phy, pdy, c);
            asm volatile("cp.async.commit_group;\n");
        }
    }
}

// ---------------------------------------------------------------------------
extern "C" void kernel_launch(void* const* d_in, const int* in_sizes, int n_in,
                              void* d_out, int out_size)
{
    const float* x_phy = (const float*)d_in[0];   // [730,10000,3]
    const float* ac    = (const float*)d_in[1];   // [10000]
    // d_in[2] = elev_all (unused by the model)
    const float* pdy   = (const float*)d_in[3];   // [730,10000,4]
    const float* pstat = (const float*)d_in[4];   // [10000,30]
    float* out = (float*)d_out;                   // [730,10000,1]

    hbv_fused<<<(N_GRID + GPB - 1) / GPB, BLK>>>(x_phy, ac, pdy, pstat, out);
}

// round 5
// speedup vs baseline: 1.3006x; 1.3006x over previous
#include <cuda_runtime.h>

#define T_STEPS 730
#define N_GRID  10000
#define LENF    15
#define NEARZERO 1e-5f
#define BLK   128           // threads per block (2 per cell)
#define GPB   64            // grid cells per block
#define CHUNK 14            // timesteps per cp.async stage (== routing-ring period)
#define NCH   53            // ceil(730/14); last chunk only 2 live steps

// Shared staging: [buf][step][data]
struct __align__(16) Smem {
    float sx[2][CHUNK][GPB * 3];   // P, Ta, PET per cell
    float sd[2][CHUNK][GPB * 4];   // parBETA(m0,m1), parBETAET(m0,m1)
};

#define XVECS 6   // ceil(CHUNK*48/BLK)  (48 16B-vecs per step of x)
#define DVECS 7   // CHUNK*64/BLK        (64 16B-vecs per step of d)

__device__ __forceinline__ void cp16(unsigned dst_smem, const void* src) {
    asm volatile("cp.async.ca.shared.global [%0], [%1], 16;\n" :: "r"(dst_smem), "l"(src));
}

// Per-component HBV parameters + state
struct Chain {
    float parFC, parK0, parK1, parK2, parPERC, parUZL, parTT,
          parCFMAX, parCWH, parC;
    float invFC, invLPFC, crf, gwcap;
};

// One HBV step + inline 15-tap gamma-UH routing.
// RP = t mod 14 (compile-time) -> static ring indexing.
template<int RP>
__device__ __forceinline__ void step_body(
    const Chain& S, float& snowpack, float& meltwater, float& sm, float& suz, float& slz,
    float (&w)[LENF], float (&qh)[LENF - 1],
    const float* __restrict__ px, const float* __restrict__ pd0, const float* __restrict__ pd1,
    int t, int g, bool active, float* __restrict__ out)
{
    const float P  = px[RP * (GPB * 3) + 0];
    const float Ta = px[RP * (GPB * 3) + 1];
    const float PE = px[RP * (GPB * 3) + 2];
    const float beta   = pd0[RP * (GPB * 4)] * 5.0f + 1.0f;   // [1,6]
    const float betaet = pd1[RP * (GPB * 4)] * 4.7f + 0.3f;   // [0.3,5]

    // --- snow bucket ---
    const float rain = (Ta >= S.parTT) ? P : 0.0f;
    const float snow = P - rain;
    snowpack += snow;
    const float melt = fminf(fmaxf(S.parCFMAX * (Ta - S.parTT), 0.0f), snowpack);
    meltwater += melt;
    snowpack  -= melt;
    const float refr = fminf(fmaxf(S.crf * (S.parTT - Ta), 0.0f), meltwater);
    snowpack  += refr;
    meltwater -= refr;
    const float tosoil = fmaxf(meltwater - S.parCWH * snowpack, 0.0f);
    meltwater -= tosoil;

    // --- soil bucket ---
    const float swet = fminf(__powf(sm * S.invFC, beta), 1.0f);
    const float rpt  = rain + tosoil;
    const float recharge = rpt * swet;
    sm += rpt - recharge;
    const float excess = fmaxf(sm - S.parFC, 0.0f);
    sm -= excess;
    const float efb = fminf(sm * S.invLPFC, 1.0f);
    const float ef  = __powf(efb, betaet);
    const float et  = fminf(sm, PE * ef);
    sm = fmaxf(sm - et, NEARZERO);
    const float cap = fminf(slz, S.parC * slz * (1.0f - fminf(sm * S.invFC, 1.0f)));
    sm  = fmaxf(sm + cap, NEARZERO);
    slz = fmaxf(slz - cap, NEARZERO);

    // --- groundwater buckets ---
    suz += recharge + excess;
    const float perc = fminf(suz, S.parPERC);
    suz -= perc;
    const float q0 = S.parK0 * fmaxf(suz - S.parUZL, 0.0f);
    suz -= q0;
    const float q1 = S.parK1 * suz;
    suz -= q1;
    slz += perc;
    const float gwl = fminf(slz, S.gwcap);
    slz -= gwl;
    const float q2 = S.parK2 * slz;
    slz -= q2;

    const float qt = q0 + q1 + q2;
    const float qs = 0.5f * (qt + __shfl_xor_sync(0xffffffffu, qt, 1));

    // --- routing: flow[t] = w0*q[t] + sum_{k=1..14} w[k]*q[t-k] ---
    float flow = w[0] * qs;
    #pragma unroll
    for (int k = 1; k < LENF; ++k)
        flow += w[k] * qh[(RP + 14 - k) % 14];
    qh[RP] = qs;

    if (active) out[t * N_GRID + g] = flow;
}

__global__ void __launch_bounds__(BLK) hbv_fused(
    const float* __restrict__ x_phy,   // [T, G, 3]
    const float* __restrict__ ac_all,  // [G]
    const float* __restrict__ pdy,     // [T, G, 2, 2]
    const float* __restrict__ pstat,   // [G, 30]
    float* __restrict__ out)           // [T, G]
{
    __shared__ Smem smem;

    const int gb  = blockIdx.x * GPB;
    const int lg  = threadIdx.x >> 1;
    const int m   = threadIdx.x & 1;
    const int g   = gb + lg;
    const bool active = (g < N_GRID) && (m == 0);
    const int gc  = (g < N_GRID) ? g : (N_GRID - 1);
    const int c   = threadIdx.x;

    // ---------- staging address precompute (loop-invariant) ----------
    // x: CHUNK*48 16B-vecs; d: CHUNK*64 16B-vecs; thread c handles vec c + v*BLK.
    int xoff[XVECS];  unsigned xdst[XVECS];
    #pragma unroll
    for (int v = 0; v < XVECS; ++v) {
        const int i = c + v * BLK;
        const int st = i / 48, o = i % 48;
        xoff[v] = st * (N_GRID * 3) + gb * 3 + o * 4;          // element offset at t0=0
        xdst[v] = (unsigned)__cvta_generic_to_shared(&smem.sx[0][st][o * 4]);
    }
    int doff[DVECS];  unsigned ddst[DVECS];
    #pragma unroll
    for (int v = 0; v < DVECS; ++v) {
        const int i = c + v * BLK;
        const int st = i >> 6, o = i & 63;
        doff[v] = st * (N_GRID * 4) + gb * 4 + o * 4;
        ddst[v] = (unsigned)__cvta_generic_to_shared(&smem.sd[0][st][o * 4]);
    }
    const unsigned xbufstride = (unsigned)(sizeof(float) * CHUNK * GPB * 3);
    const unsigned dbufstride = (unsigned)(sizeof(float) * CHUNK * GPB * 4);
    const int limx = T_STEPS * N_GRID * 3 - 4;
    const int limd = T_STEPS * N_GRID * 4 - 4;

    auto stage = [&](int ch) {
        const unsigned bsel = (unsigned)(ch & 1);
        const int bx = ch * (CHUNK * N_GRID * 3);
        const int bd = ch * (CHUNK * N_GRID * 4);
        #pragma unroll
        for (int v = 0; v < XVECS; ++v) {
            if (c + v * BLK < CHUNK * 48) {
                int idx = bx + xoff[v];
                idx = (idx > limx) ? limx : idx;
                cp16(xdst[v] + bsel * xbufstride, x_phy + idx);
            }
        }
        #pragma unroll
        for (int v = 0; v < DVECS; ++v) {
            int idx = bd + doff[v];
            idx = (idx > limd) ? limd : idx;
            cp16(ddst[v] + bsel * dbufstride, pdy + idx);
        }
    };

    // ---------- static params ----------
    const float* ps = pstat + gc * 30;
    const float Ac = ac_all[gc];
    Chain S;
    S.parFC    = ps[0*2+m]  * 950.0f  + 50.0f;
    S.parK0    = ps[1*2+m]  * 0.85f   + 0.05f;
    S.parK1    = ps[2*2+m]  * 0.49f   + 0.01f;
    S.parK2    = ps[3*2+m]  * 0.199f  + 0.001f;
    const float parLP = ps[4*2+m] * 0.8f + 0.2f;
    S.parPERC  = ps[5*2+m]  * 10.0f;
    S.parUZL   = ps[6*2+m]  * 100.0f;
    S.parTT    = ps[7*2+m]  * 5.0f    - 2.5f;
    S.parCFMAX = ps[8*2+m]  * 9.5f    + 0.5f;
    const float parCFR = ps[9*2+m] * 0.1f;
    S.parCWH   = ps[10*2+m] * 0.2f;
    S.parC     = ps[11*2+m];
    const float parRT = ps[12*2+m] * 20.0f;
    const float parAC = ps[13*2+m] * 2500.0f;
    S.invFC   = 1.0f / S.parFC;
    S.invLPFC = 1.0f / (parLP * S.parFC);
    S.crf     = parCFR * S.parCFMAX;
    S.gwcap   = parRT * fminf(fmaxf(1.0f - Ac / (parAC + NEARZERO), 0.0f), 1.0f);

    // ---------- normalized gamma-UH weights ----------
    const float a_r  = fmaxf(ps[28] * 2.9f, 0.0f) + 0.1f;
    const float th_r = fmaxf(ps[29] * 6.5f, 0.0f) + 0.5f;
    const float am1  = a_r - 1.0f;
    const float ivt  = 1.0f / th_r;
    const float LOGTK[LENF] = {
        -0.69314718f, 0.40546511f, 0.91629073f, 1.25276297f, 1.50407740f,
         1.70474809f, 1.87180218f, 2.01490302f, 2.14006616f, 2.25129180f,
         2.35137526f, 2.44234704f, 2.52572864f, 2.60268969f, 2.67414865f };
    float w[LENF];
    float wsum = 0.0f;
    #pragma unroll
    for (int k = 0; k < LENF; ++k) {
        const float tk = (float)k + 0.5f;
        w[k] = __expf(am1 * LOGTK[k] - tk * ivt);
        wsum += w[k];
    }
    const float ivw = 1.0f / wsum;
    #pragma unroll
    for (int k = 0; k < LENF; ++k) w[k] *= ivw;

    // ---------- state ----------
    float snowpack = 1e-3f, meltwater = 1e-3f, sm = 1e-3f, suz = 1e-3f, slz = 1e-3f;
    float qh[LENF - 1];
    #pragma unroll
    for (int k = 0; k < LENF - 1; ++k) qh[k] = 0.0f;

    // shared read base pointers for this thread
    const float* px0 = &smem.sx[0][0][lg * 3];
    const float* pda = &smem.sd[0][0][lg * 4 + m];       // beta
    const float* pdb = &smem.sd[0][0][lg * 4 + 2 + m];   // betaet

    // ---------- pipeline prologue ----------
    stage(0);
    asm volatile("cp.async.commit_group;\n");
    stage(1);
    asm volatile("cp.async.commit_group;\n");

    // ---------- main loop: 52 chunks x 14 steps ----------
    for (int ch = 0; ch < NCH - 1; ++ch) {
        asm volatile("cp.async.wait_group 1;\n");
        __syncthreads();

        const int buf = ch & 1;
        const float* px = px0 + buf * (CHUNK * GPB * 3);
        const float* p0 = pda + buf * (CHUNK * GPB * 4);
        const float* p1 = pdb + buf * (CHUNK * GPB * 4);
        const int t0 = ch * CHUNK;

        step_body< 0>(S, snowpack, meltwater, sm, suz, slz, w, qh, px, p0, p1, t0 +  0, g, active, out);
        step_body< 1>(S, snowpack, meltwater, sm, suz, slz, w, qh, px, p0, p1, t0 +  1, g, active, out);
        step_body< 2>(S, snowpack, meltwater, sm, suz, slz, w, qh, px, p0, p1, t0 +  2, g, active, out);
        step_body< 3>(S, snowpack, meltwater, sm, suz, slz, w, qh, px, p0, p1, t0 +  3, g, active, out);
        step_body< 4>(S, snowpack, meltwater, sm, suz, slz, w, qh, px, p0, p1, t0 +  4, g, active, out);
        step_body< 5>(S, snowpack, meltwater, sm, suz, slz, w, qh, px, p0, p1, t0 +  5, g, active, out);
        step_body< 6>(S, snowpack, meltwater, sm, suz, slz, w, qh, px, p0, p1, t0 +  6, g, active, out);
        step_body< 7>(S, snowpack, meltwater, sm, suz, slz, w, qh, px, p0, p1, t0 +  7, g, active, out);
        step_body< 8>(S, snowpack, meltwater, sm, suz, slz, w, qh, px, p0, p1, t0 +  8, g, active, out);
        step_body< 9>(S, snowpack, meltwater, sm, suz, slz, w, qh, px, p0, p1, t0 +  9, g, active, out);
        step_body<10>(S, snowpack, meltwater, sm, suz, slz, w, qh, px, p0, p1, t0 + 10, g, active, out);
        step_body<11>(S, snowpack, meltwater, sm, suz, slz, w, qh, px, p0, p1, t0 + 11, g, active, out);
        step_body<12>(S, snowpack, meltwater, sm, suz, slz, w, qh, px, p0, p1, t0 + 12, g, active, out);
        step_body<13>(S, snowpack, meltwater, sm, suz, slz, w, qh, px, p0, p1, t0 + 13, g, active, out);

        __syncthreads();
        if (ch + 2 < NCH) stage(ch + 2);
        asm volatile("cp.async.commit_group;\n");
    }

    // ---------- epilogue: chunk 52, live steps 728..729 only ----------
    asm volatile("cp.async.wait_group 0;\n");
    __syncthreads();
    {
        const int buf = (NCH - 1) & 1;   // = 0
        const float* px = px0 + buf * (CHUNK * GPB * 3);
        const float* p0 = pda + buf * (CHUNK * GPB * 4);
        const float* p1 = pdb + buf * (CHUNK * GPB * 4);
        const int t0 = (NCH - 1) * CHUNK;  // 728
        step_body<0>(S, snowpack, meltwater, sm, suz, slz, w, qh, px, p0, p1, t0 + 0, g, active, out);
        step_body<1>(S, snowpack, meltwater, sm, suz, slz, w, qh, px, p0, p1, t0 + 1, g, active, out);
    }
}

// ---------------------------------------------------------------------------
extern "C" void kernel_launch(void* const* d_in, const int* in_sizes, int n_in,
                              void* d_out, int out_size)
{
    const float* x_phy = (const float*)d_in[0];   // [730,10000,3]
    const float* ac    = (const float*)d_in[1];   // [10000]
    // d_in[2] = elev_all (unused)
    const float* pdy   = (const float*)d_in[3];   // [730,10000,4]
    const float* pstat = (const float*)d_in[4];   // [10000,30]
    float* out = (float*)d_out;                   // [730,10000,1]

    hbv_fused<<<(2 * N_GRID + BLK - 1) / BLK, BLK>>>(x_phy, ac, pdy, pstat, out);
}

// round 6
// speedup vs baseline: 1.6517x; 1.2700x over previous
#include <cuda_runtime.h>

#define T_STEPS 730
#define N_GRID  10000
#define LENF    15
#define NEARZERO 1e-5f
#define BLK   128           // threads per block (2 per cell)
#define GPB   64            // grid cells per block
#define CHUNK 7             // timesteps per stage == routing-ring period
#define NCHUNKS 105         // ceil(730/7); chunk 104 has 2 live steps

// Shared staging: [buf][step][data]
struct __align__(16) Smem {
    float sx[2][CHUNK][GPB * 3];   // P, Ta, PET per cell
    float sd[2][CHUNK][GPB * 4];   // parBETA(m0,m1), parBETAET(m0,m1)
};

__device__ __forceinline__ void cp16(void* dst_smem, const void* src) {
    unsigned d = (unsigned)__cvta_generic_to_shared(dst_smem);
    asm volatile("cp.async.ca.shared.global [%0], [%1], 16;\n" :: "r"(d), "l"(src));
}

// Stage CHUNK timesteps of chunk `ch` into buffer ch&1.
// Addresses clamped to tensor end; clamped data never used for output.
__device__ __forceinline__ void stage(
    Smem& s, int ch, int gb,
    const float* __restrict__ x_phy, const float* __restrict__ pdy, int c)
{
    const int buf = ch & 1;
    const int t0  = ch * CHUNK;
    const int limx = T_STEPS * N_GRID * 3 - 4;
    #pragma unroll
    for (int v = 0; v < 3; ++v) {                 // CHUNK*48 = 336 vecs / 128 thr
        const int i = c + v * BLK;
        if (i < CHUNK * 48) {
            const int st = i / 48, o = i % 48;
            int idx = (t0 + st) * (N_GRID * 3) + gb * 3 + o * 4;
            idx = (idx > limx) ? limx : idx;
            cp16(&s.sx[buf][st][o * 4], x_phy + idx);
        }
    }
    const int limd = T_STEPS * N_GRID * 4 - 4;
    #pragma unroll
    for (int v = 0; v < 4; ++v) {                 // CHUNK*64 = 448 vecs / 128 thr
        const int i = c + v * BLK;
        if (i < CHUNK * 64) {
            const int st = i >> 6, o = i & 63;
            int idx = (t0 + st) * (N_GRID * 4) + gb * 4 + o * 4;
            idx = (idx > limd) ? limd : idx;
            cp16(&s.sd[buf][st][o * 4], pdy + idx);
        }
    }
}

// Per-component HBV parameters
struct Chain {
    float parFC, parK0, parK1, parK2, parPERC, parUZL, parTT,
          parCFMAX, parCWH, parC;
    float invFC, invLPFC, crf, gwcap;
};

// One HBV step + split 15-tap gamma-UH routing (taps 0-7 on m0, 8-14 on m1).
// RP = t mod 7 (compile-time) -> static ring indexing, zero register moves.
template<int RP>
__device__ __forceinline__ void step_body(
    const Chain& S, float& snowpack, float& meltwater, float& sm, float& suz, float& slz,
    const float w0eff, const float (&wv)[7], float (&rq)[7], int m,
    const float* __restrict__ px, const float* __restrict__ pd0, const float* __restrict__ pd1,
    bool store_ok, float* __restrict__ outp)
{
    const float P  = px[RP * (GPB * 3) + 0];
    const float Ta = px[RP * (GPB * 3) + 1];
    const float PE = px[RP * (GPB * 3) + 2];
    const float beta   = pd0[RP * (GPB * 4)] * 5.0f + 1.0f;   // [1,6]
    const float betaet = pd1[RP * (GPB * 4)] * 4.7f + 0.3f;   // [0.3,5]

    // --- snow bucket ---
    const float rain = (Ta >= S.parTT) ? P : 0.0f;
    const float snow = P - rain;
    snowpack += snow;
    const float melt = fminf(fmaxf(S.parCFMAX * (Ta - S.parTT), 0.0f), snowpack);
    meltwater += melt;
    snowpack  -= melt;
    const float refr = fminf(fmaxf(S.crf * (S.parTT - Ta), 0.0f), meltwater);
    snowpack  += refr;
    meltwater -= refr;
    const float tosoil = fmaxf(meltwater - S.parCWH * snowpack, 0.0f);
    meltwater -= tosoil;

    // --- soil bucket ---
    const float swet = fminf(__powf(sm * S.invFC, beta), 1.0f);
    const float rpt  = rain + tosoil;
    const float recharge = rpt * swet;
    sm += rpt - recharge;
    const float excess = fmaxf(sm - S.parFC, 0.0f);
    sm -= excess;
    const float efb = fminf(sm * S.invLPFC, 1.0f);
    const float ef  = __powf(efb, betaet);
    const float et  = fminf(sm, PE * ef);
    sm = fmaxf(sm - et, NEARZERO);
    const float cap = fminf(slz, S.parC * slz * (1.0f - fminf(sm * S.invFC, 1.0f)));
    sm  = fmaxf(sm + cap, NEARZERO);
    slz = fmaxf(slz - cap, NEARZERO);

    // --- groundwater buckets ---
    suz += recharge + excess;
    const float perc = fminf(suz, S.parPERC);
    suz -= perc;
    const float q0 = S.parK0 * fmaxf(suz - S.parUZL, 0.0f);
    suz -= q0;
    const float q1 = S.parK1 * suz;
    suz -= q1;
    slz += perc;
    const float gwl = fminf(slz, S.gwcap);
    slz -= gwl;
    const float q2 = S.parK2 * slz;
    slz -= q2;

    const float qt = q0 + q1 + q2;
    const float qs = 0.5f * (qt + __shfl_xor_sync(0xffffffffu, qt, 1));

    // --- split routing ---
    // m0 ring holds q[t-1..t-7]; m1 ring holds q[t-8..t-14] (slot = time mod 7).
    const float evict = rq[RP];                                   // m0: q[t-7]; m1: q[t-14]
    const float incoming = __shfl_xor_sync(0xffffffffu, evict, 1); // m1 receives m0's q[t-7]
    float partial = w0eff * qs;                                   // w0 tap (m0 only; m1 w0eff=0)
    #pragma unroll
    for (int j = 1; j <= 7; ++j)
        partial += wv[j - 1] * rq[(RP + 7 - j) % 7];              // taps j (m0) / 7+j (m1)
    rq[RP] = m ? incoming : qs;
    const float flow = partial + __shfl_xor_sync(0xffffffffu, partial, 1);

    if (store_ok) outp[RP * N_GRID] = flow;
}

__global__ void __launch_bounds__(BLK) hbv_fused(
    const float* __restrict__ x_phy,   // [T, G, 3]
    const float* __restrict__ ac_all,  // [G]
    const float* __restrict__ pdy,     // [T, G, 2, 2]
    const float* __restrict__ pstat,   // [G, 30]
    float* __restrict__ out)           // [T, G]
{
    __shared__ Smem smem;

    const int gb  = blockIdx.x * GPB;
    const int lg  = threadIdx.x >> 1;
    const int m   = threadIdx.x & 1;
    const int g   = gb + lg;
    const bool store_ok = (g < N_GRID) && (m == 0);
    const int gc  = (g < N_GRID) ? g : (N_GRID - 1);
    const int c   = threadIdx.x;

    // ---------- static params ----------
    const float* ps = pstat + gc * 30;
    const float Ac = ac_all[gc];
    Chain S;
    S.parFC    = ps[0*2+m]  * 950.0f  + 50.0f;
    S.parK0    = ps[1*2+m]  * 0.85f   + 0.05f;
    S.parK1    = ps[2*2+m]  * 0.49f   + 0.01f;
    S.parK2    = ps[3*2+m]  * 0.199f  + 0.001f;
    const float parLP = ps[4*2+m] * 0.8f + 0.2f;
    S.parPERC  = ps[5*2+m]  * 10.0f;
    S.parUZL   = ps[6*2+m]  * 100.0f;
    S.parTT    = ps[7*2+m]  * 5.0f    - 2.5f;
    S.parCFMAX = ps[8*2+m]  * 9.5f    + 0.5f;
    const float parCFR = ps[9*2+m] * 0.1f;
    S.parCWH   = ps[10*2+m] * 0.2f;
    S.parC     = ps[11*2+m];
    const float parRT = ps[12*2+m] * 20.0f;
    const float parAC = ps[13*2+m] * 2500.0f;
    S.invFC   = 1.0f / S.parFC;
    S.invLPFC = 1.0f / (parLP * S.parFC);
    S.crf     = parCFR * S.parCFMAX;
    S.gwcap   = parRT * fminf(fmaxf(1.0f - Ac / (parAC + NEARZERO), 0.0f), 1.0f);

    // ---------- normalized gamma-UH weights, split across the thread pair ----------
    // Normalization cancels exp(-lgamma(a)) * theta^(-a):
    // w[k] ∝ exp((a-1)*ln(k+0.5) - (k+0.5)/theta)
    const float a_r  = fmaxf(ps[28] * 2.9f, 0.0f) + 0.1f;
    const float th_r = fmaxf(ps[29] * 6.5f, 0.0f) + 0.5f;
    const float am1  = a_r - 1.0f;
    const float ivt  = 1.0f / th_r;
    const float LOGTK[LENF] = {
        -0.69314718f, 0.40546511f, 0.91629073f, 1.25276297f, 1.50407740f,
         1.70474809f, 1.87180218f, 2.01490302f, 2.14006616f, 2.25129180f,
         2.35137526f, 2.44234704f, 2.52572864f, 2.60268969f, 2.67414865f };
    float wfull[LENF];
    float wsum = 0.0f;
    #pragma unroll
    for (int k = 0; k < LENF; ++k) {
        const float tk = (float)k + 0.5f;
        wfull[k] = __expf(am1 * LOGTK[k] - tk * ivt);
        wsum += wfull[k];
    }
    const float ivw = 1.0f / wsum;
    // thread m=0 keeps taps 0..7; thread m=1 keeps taps 8..14
    const float w0eff = m ? 0.0f : wfull[0] * ivw;
    float wv[7];
    #pragma unroll
    for (int j = 1; j <= 7; ++j)
        wv[j - 1] = wfull[m ? (7 + j) : j] * ivw;

    // ---------- state ----------
    float snowpack = 1e-3f, meltwater = 1e-3f, sm = 1e-3f, suz = 1e-3f, slz = 1e-3f;
    float rq[7];
    #pragma unroll
    for (int k = 0; k < 7; ++k) rq[k] = 0.0f;

    // shared read base pointers for this thread
    const float* px0 = &smem.sx[0][0][lg * 3];
    const float* pda = &smem.sd[0][0][lg * 4 + m];       // beta
    const float* pdb = &smem.sd[0][0][lg * 4 + 2 + m];   // betaet
    const int xstride = CHUNK * GPB * 3;
    const int dstride = CHUNK * GPB * 4;

    // ---------- pipeline prologue ----------
    stage(smem, 0, gb, x_phy, pdy, c);
    asm volatile("cp.async.commit_group;\n");
    stage(smem, 1, gb, x_phy, pdy, c);
    asm volatile("cp.async.commit_group;\n");

    // ---------- main loop: 104 full chunks (t = 0..727) ----------
    for (int ch = 0; ch < NCHUNKS - 1; ++ch) {
        asm volatile("cp.async.wait_group 1;\n");
        __syncthreads();

        const int buf = ch & 1;
        const float* px = px0 + buf * xstride;
        const float* p0 = pda + buf * dstride;
        const float* p1 = pdb + buf * dstride;
        float* outp = out + ch * (CHUNK * N_GRID) + g;

        step_body<0>(S, snowpack, meltwater, sm, suz, slz, w0eff, wv, rq, m, px, p0, p1, store_ok, outp);
        step_body<1>(S, snowpack, meltwater, sm, suz, slz, w0eff, wv, rq, m, px, p0, p1, store_ok, outp);
        step_body<2>(S, snowpack, meltwater, sm, suz, slz, w0eff, wv, rq, m, px, p0, p1, store_ok, outp);
        step_body<3>(S, snowpack, meltwater, sm, suz, slz, w0eff, wv, rq, m, px, p0, p1, store_ok, outp);
        step_body<4>(S, snowpack, meltwater, sm, suz, slz, w0eff, wv, rq, m, px, p0, p1, store_ok, outp);
        step_body<5>(S, snowpack, meltwater, sm, suz, slz, w0eff, wv, rq, m, px, p0, p1, store_ok, outp);
        step_body<6>(S, snowpack, meltwater, sm, suz, slz, w0eff, wv, rq, m, px, p0, p1, store_ok, outp);

        __syncthreads();
        if (ch + 2 < NCHUNKS) stage(smem, ch + 2, gb, x_phy, pdy, c);
        asm volatile("cp.async.commit_group;\n");
    }

    // ---------- epilogue: chunk 104, live steps 728..729 ----------
    asm volatile("cp.async.wait_group 0;\n");
    __syncthreads();
    {
        const int ch = NCHUNKS - 1;        // 104, buf 0
        const int buf = ch & 1;
        const float* px = px0 + buf * xstride;
        const float* p0 = pda + buf * dstride;
        const float* p1 = pdb + buf * dstride;
        float* outp = out + ch * (CHUNK * N_GRID) + g;
        step_body<0>(S, snowpack, meltwater, sm, suz, slz, w0eff, wv, rq, m, px, p0, p1, store_ok, outp);
        step_body<1>(S, snowpack, meltwater, sm, suz, slz, w0eff, wv, rq, m, px, p0, p1, store_ok, outp);
    }
}

// ---------------------------------------------------------------------------
extern "C" void kernel_launch(void* const* d_in, const int* in_sizes, int n_in,
                              void* d_out, int out_size)
{
    const float* x_phy = (const float*)d_in[0];   // [730,10000,3]
    const float* ac    = (const float*)d_in[1];   // [10000]
    // d_in[2] = elev_all (unused)
    const float* pdy   = (const float*)d_in[3];   // [730,10000,4]
    const float* pstat = (const float*)d_in[4];   // [10000,30]
    float* out = (float*)d_out;                   // [730,10000,1]

    hbv_fused<<<(2 * N_GRID + BLK - 1) / BLK, BLK>>>(x_phy, ac, pdy, pstat, out);
}

// round 7
// speedup vs baseline: 1.7166x; 1.0393x over previous
#include <cuda_runtime.h>

#define T_STEPS 730
#define N_GRID  10000
#define LENF    15
#define NEARZERO 1e-5f
#define BLK   128           // threads per block (2 per cell)
#define GPB   64            // grid cells per block
#define CHUNK 7             // timesteps per stage
#define NCHUNKS 105         // ceil(730/7); chunk 104 has 2 live steps

// Shared staging: [buf][step][data]
struct __align__(16) Smem {
    float sx[2][CHUNK][GPB * 3];   // P, Ta, PET per cell
    float sd[2][CHUNK][GPB * 4];   // parBETA(m0,m1), parBETAET(m0,m1)
};

__device__ __forceinline__ void cp16(void* dst_smem, const void* src) {
    unsigned d = (unsigned)__cvta_generic_to_shared(dst_smem);
    asm volatile("cp.async.ca.shared.global [%0], [%1], 16;\n" :: "r"(d), "l"(src));
}

__device__ __forceinline__ float lg2a(float x) {
    float r; asm("lg2.approx.f32 %0, %1;" : "=f"(r) : "f"(x)); return r;
}
__device__ __forceinline__ float ex2a(float x) {
    float r; asm("ex2.approx.f32 %0, %1;" : "=f"(r) : "f"(x)); return r;
}

// Stage CHUNK timesteps of chunk `ch` into buffer ch&1 (addresses clamped).
__device__ __forceinline__ void stage(
    Smem& s, int ch, int gb,
    const float* __restrict__ x_phy, const float* __restrict__ pdy, int c)
{
    const int buf = ch & 1;
    const int t0  = ch * CHUNK;
    const int limx = T_STEPS * N_GRID * 3 - 4;
    #pragma unroll
    for (int v = 0; v < 3; ++v) {
        const int i = c + v * BLK;
        if (i < CHUNK * 48) {
            const int st = i / 48, o = i % 48;
            int idx = (t0 + st) * (N_GRID * 3) + gb * 3 + o * 4;
            idx = (idx > limx) ? limx : idx;
            cp16(&s.sx[buf][st][o * 4], x_phy + idx);
        }
    }
    const int limd = T_STEPS * N_GRID * 4 - 4;
    #pragma unroll
    for (int v = 0; v < 4; ++v) {
        const int i = c + v * BLK;
        if (i < CHUNK * 64) {
            const int st = i >> 6, o = i & 63;
            int idx = (t0 + st) * (N_GRID * 4) + gb * 4 + o * 4;
            idx = (idx > limd) ? limd : idx;
            cp16(&s.sd[buf][st][o * 4], pdy + idx);
        }
    }
}

// Per-component HBV parameters (hoisted/precombined)
struct Chain {
    float parFC, parK0, parK1, parK2, parPERC, parUZL, parTT,
          parCFMAX, parCWH, parC;
    float invFC, invLPFC, crf, gwcap, cfmaxTT, crfTT;
};

// One HBV step + per-component 15-tap routing (weights pre-scaled by 0.5).
// RP = t mod 14 (compile-time): static ring indexing. Slot in buffer = RP%7.
template<int RP>
__device__ __forceinline__ void step_body(
    const Chain& S, float& snowpack, float& meltwater, float& sm, float& suz,
    float& slz, float& lsm,
    const float (&w)[LENF], float (&qh)[14],
    const float* __restrict__ px, const float* __restrict__ pd0,
    const float* __restrict__ pd1,
    bool store_ok, float* __restrict__ outp)
{
    constexpr int SL = RP % 7;
    const float P  = px[SL * (GPB * 3) + 0];
    const float Ta = px[SL * (GPB * 3) + 1];
    const float PE = px[SL * (GPB * 3) + 2];
    const float beta   = pd0[SL * (GPB * 4)] * 5.0f + 1.0f;   // [1,6]
    const float betaet = pd1[SL * (GPB * 4)] * 4.7f + 0.3f;   // [0.3,5]

    // swet from carried lsm = lg2(sm_prev * invFC)   (head of step is just FMUL+EX2)
    const float swet = __saturatef(ex2a(beta * lsm));

    // --- snow bucket ---
    const bool wet = (Ta >= S.parTT);
    const float rain = wet ? P : 0.0f;
    const float snow = wet ? 0.0f : P;
    const float melt0 = fmaxf(fmaf(S.parCFMAX, Ta, -S.cfmaxTT), 0.0f);
    const float refr0 = fmaxf(fmaf(-S.crf, Ta, S.crfTT), 0.0f);
    float sp1 = snowpack + snow;
    const float melt = fminf(melt0, sp1);
    float mw1 = meltwater + melt;
    sp1 -= melt;
    const float refr = fminf(refr0, mw1);
    sp1 += refr;
    mw1 -= refr;
    const float tosoil = fmaxf(fmaf(-S.parCWH, sp1, mw1), 0.0f);
    snowpack = sp1;
    meltwater = mw1 - tosoil;

    // --- soil bucket ---
    const float rpt = rain + tosoil;
    const float recharge = rpt * swet;
    const float sm1 = sm + (rpt - recharge);
    const float sm2 = fminf(sm1, S.parFC);          // excess removal
    const float excess = sm1 - sm2;                 // off-chain
    const float efb = __saturatef(sm2 * S.invLPFC);
    const float ef  = ex2a(betaet * lg2a(efb));
    const float sm3 = fmaxf(fmaf(-PE, ef, sm2), NEARZERO);   // == max(sm2 - min(sm2,PE*ef), NZ)
    const float cslz = S.parC * slz;                // off-chain (slz is prev-step value)
    const float f1  = 1.0f - __saturatef(sm3 * S.invFC);
    const float cap = fminf(cslz * f1, slz);
    const float sm4 = fmaxf(sm3 + cap, NEARZERO);
    float slz2 = fmaxf(slz - cap, NEARZERO);
    sm = sm4;
    lsm = lg2a(sm4 * S.invFC);                      // tail: feeds next step's swet

    // --- groundwater buckets ---
    const float suz1 = suz + (recharge + excess);
    const float perc = fminf(suz1, S.parPERC);
    const float suz2 = suz1 - perc;
    const float q0 = S.parK0 * fmaxf(suz2 - S.parUZL, 0.0f);
    const float suz3 = suz2 - q0;
    const float q1 = S.parK1 * suz3;
    suz = suz3 - q1;
    const float slzp = slz2 + perc;
    const float slza = fmaxf(slzp - S.gwcap, 0.0f); // == slzp - min(slzp, gwcap)
    const float q2 = S.parK2 * slza;
    slz = slza - q2;
    const float qt = (q0 + q1) + q2;

    // --- routing: each thread routes ITS OWN component (w pre-scaled by 0.5);
    //     flow = own partial + sibling partial (one shfl). Ring slot = t mod 14.
    float a0 = w[0] * qt;
    float a1 = w[5] * qh[(RP + 14 - 5) % 14];
    float a2 = w[10] * qh[(RP + 14 - 10) % 14];
    #pragma unroll
    for (int k = 1; k <= 4; ++k)  a0 = fmaf(w[k], qh[(RP + 14 - k) % 14], a0);
    #pragma unroll
    for (int k = 6; k <= 9; ++k)  a1 = fmaf(w[k], qh[(RP + 14 - k) % 14], a1);
    #pragma unroll
    for (int k = 11; k <= 14; ++k) a2 = fmaf(w[k], qh[(RP + 14 - k) % 14], a2);
    qh[RP] = qt;
    const float partial = (a0 + a1) + a2;
    const float flow = partial + __shfl_xor_sync(0xffffffffu, partial, 1);

    if (store_ok) outp[SL * N_GRID] = flow;
}

__global__ void __launch_bounds__(BLK) hbv_fused(
    const float* __restrict__ x_phy,   // [T, G, 3]
    const float* __restrict__ ac_all,  // [G]
    const float* __restrict__ pdy,     // [T, G, 2, 2]
    const float* __restrict__ pstat,   // [G, 30]
    float* __restrict__ out)           // [T, G]
{
    __shared__ Smem smem;

    const int gb  = blockIdx.x * GPB;
    const int lg  = threadIdx.x >> 1;
    const int m   = threadIdx.x & 1;
    const int g   = gb + lg;
    const bool store_ok = (g < N_GRID) && (m == 0);
    const int gc  = (g < N_GRID) ? g : (N_GRID - 1);
    const int c   = threadIdx.x;

    // ---------- static params ----------
    const float* ps = pstat + gc * 30;
    const float Ac = ac_all[gc];
    Chain S;
    S.parFC    = ps[0*2+m]  * 950.0f  + 50.0f;
    S.parK0    = ps[1*2+m]  * 0.85f   + 0.05f;
    S.parK1    = ps[2*2+m]  * 0.49f   + 0.01f;
    S.parK2    = ps[3*2+m]  * 0.199f  + 0.001f;
    const float parLP = ps[4*2+m] * 0.8f + 0.2f;
    S.parPERC  = ps[5*2+m]  * 10.0f;
    S.parUZL   = ps[6*2+m]  * 100.0f;
    S.parTT    = ps[7*2+m]  * 5.0f    - 2.5f;
    S.parCFMAX = ps[8*2+m]  * 9.5f    + 0.5f;
    const float parCFR = ps[9*2+m] * 0.1f;
    S.parCWH   = ps[10*2+m] * 0.2f;
    S.parC     = ps[11*2+m];
    const float parRT = ps[12*2+m] * 20.0f;
    const float parAC = ps[13*2+m] * 2500.0f;
    S.invFC   = 1.0f / S.parFC;
    S.invLPFC = 1.0f / (parLP * S.parFC);
    S.crf     = parCFR * S.parCFMAX;
    S.gwcap   = parRT * fminf(fmaxf(1.0f - Ac / (parAC + NEARZERO), 0.0f), 1.0f);
    S.cfmaxTT = S.parCFMAX * S.parTT;
    S.crfTT   = S.crf * S.parTT;

    // ---------- normalized gamma-UH weights (pre-scaled by 0.5 for the nmul mean) ----------
    // w[k] ∝ exp((a-1)·ln t_k − t_k/θ) = ex2(am1·log2 t_k − t_k·(log2e/θ))
    const float a_r  = fmaxf(ps[28] * 2.9f, 0.0f) + 0.1f;
    const float th_r = fmaxf(ps[29] * 6.5f, 0.0f) + 0.5f;
    const float am1  = a_r - 1.0f;
    const float ivtl = 1.4426950408889634f / th_r;
    const float LOG2TK[LENF] = {
        -1.0f,        0.5849625f, 1.3219281f, 1.8073549f, 2.1699250f,
         2.4594316f,  2.7004397f, 2.9068906f, 3.0874628f, 3.2479275f,
         3.3923174f,  3.5235620f, 3.6438562f, 3.7548875f, 3.8579810f };
    float w[LENF];
    float wsum = 0.0f;
    #pragma unroll
    for (int k = 0; k < LENF; ++k) {
        const float tk = (float)k + 0.5f;
        w[k] = ex2a(am1 * LOG2TK[k] - tk * ivtl);
        wsum += w[k];
    }
    const float ivw = 0.5f / wsum;   // fold the component mean into the weights
    #pragma unroll
    for (int k = 0; k < LENF; ++k) w[k] *= ivw;

    // ---------- state ----------
    float snowpack = 1e-3f, meltwater = 1e-3f, sm = 1e-3f, suz = 1e-3f, slz = 1e-3f;
    float lsm = lg2a(1e-3f * S.invFC);
    float qh[14];
    #pragma unroll
    for (int k = 0; k < 14; ++k) qh[k] = 0.0f;

    // shared read base pointers
    const float* px0 = &smem.sx[0][0][lg * 3];
    const float* pda = &smem.sd[0][0][lg * 4 + m];
    const float* pdb = &smem.sd[0][0][lg * 4 + 2 + m];
    const int xstride = CHUNK * GPB * 3;
    const int dstride = CHUNK * GPB * 4;

    // ---------- pipeline prologue ----------
    stage(smem, 0, gb, x_phy, pdy, c);
    asm volatile("cp.async.commit_group;\n");
    stage(smem, 1, gb, x_phy, pdy, c);
    asm volatile("cp.async.commit_group;\n");

    // ---------- main loop: 52 chunk-pairs (104 chunks, t = 0..727) ----------
    #define STEPS7(B) \
        step_body<B+0>(S, snowpack, meltwater, sm, suz, slz, lsm, w, qh, px, p0, p1, store_ok, outp); \
        step_body<B+1>(S, snowpack, meltwater, sm, suz, slz, lsm, w, qh, px, p0, p1, store_ok, outp); \
        step_body<B+2>(S, snowpack, meltwater, sm, suz, slz, lsm, w, qh, px, p0, p1, store_ok, outp); \
        step_body<B+3>(S, snowpack, meltwater, sm, suz, slz, lsm, w, qh, px, p0, p1, store_ok, outp); \
        step_body<B+4>(S, snowpack, meltwater, sm, suz, slz, lsm, w, qh, px, p0, p1, store_ok, outp); \
        step_body<B+5>(S, snowpack, meltwater, sm, suz, slz, lsm, w, qh, px, p0, p1, store_ok, outp); \
        step_body<B+6>(S, snowpack, meltwater, sm, suz, slz, lsm, w, qh, px, p0, p1, store_ok, outp);

    for (int p = 0; p < 52; ++p) {
        // chunk 2p (buf 0, ring phase 0..6)
        {
            asm volatile("cp.async.wait_group 1;\n");
            __syncthreads();
            const float* px = px0;
            const float* p0 = pda;
            const float* p1 = pdb;
            float* outp = out + (2 * p) * (CHUNK * N_GRID) + g;
            STEPS7(0)
            __syncthreads();
            if (2 * p + 2 < NCHUNKS) stage(smem, 2 * p + 2, gb, x_phy, pdy, c);
            asm volatile("cp.async.commit_group;\n");
        }
        // chunk 2p+1 (buf 1, ring phase 7..13)
        {
            asm volatile("cp.async.wait_group 1;\n");
            __syncthreads();
            const float* px = px0 + xstride;
            const float* p0 = pda + dstride;
            const float* p1 = pdb + dstride;
            float* outp = out + (2 * p + 1) * (CHUNK * N_GRID) + g;
            STEPS7(7)
            __syncthreads();
            if (2 * p + 3 < NCHUNKS) stage(smem, 2 * p + 3, gb, x_phy, pdy, c);
            asm volatile("cp.async.commit_group;\n");
        }
    }

    // ---------- epilogue: chunk 104 (buf 0, ring phase 0), live steps 728..729 ----------
    asm volatile("cp.async.wait_group 0;\n");
    __syncthreads();
    {
        const float* px = px0;
        const float* p0 = pda;
        const float* p1 = pdb;
        float* outp = out + 104 * (CHUNK * N_GRID) + g;
        step_body<0>(S, snowpack, meltwater, sm, suz, slz, lsm, w, qh, px, p0, p1, store_ok, outp);
        step_body<1>(S, snowpack, meltwater, sm, suz, slz, lsm, w, qh, px, p0, p1, store_ok, outp);
    }
    #undef STEPS7
}

// ---------------------------------------------------------------------------
extern "C" void kernel_launch(void* const* d_in, const int* in_sizes, int n_in,
                              void* d_out, int out_size)
{
    const float* x_phy = (const float*)d_in[0];   // [730,10000,3]
    const float* ac    = (const float*)d_in[1];   // [10000]
    // d_in[2] = elev_all (unused)
    const float* pdy   = (const float*)d_in[3];   // [730,10000,4]
    const float* pstat = (const float*)d_in[4];   // [10000,30]
    float* out = (float*)d_out;                   // [730,10000,1]

    hbv_fused<<<(2 * N_GRID + BLK - 1) / BLK, BLK>>>(x_phy, ac, pdy, pstat, out);
}